// round 3
// baseline (speedup 1.0000x reference)
#include <cuda_runtime.h>
#include <math.h>

#define DIMM 256
#define BATCH 64
#define ATOMS 512
#define ROWS (BATCH*ATOMS)   /* 32768 */
#define NLAYERS 6
#define FFD 2048
#define TT 2016
#define ACT 6
#define MAXS 63
#define NHEADS 8
#define DH 32

// ---------------- scratch (device globals; no allocation allowed) ----------
__device__ float g_x[ROWS*DIMM];        // activations (residual stream)
__device__ float g_qkv[ROWS*3*DIMM];    // qkv projections
__device__ float g_attn[ROWS*DIMM];     // attention output (pre out-proj)
__device__ float g_tmp[ROWS*DIMM];      // proj / ff2 output
__device__ float g_ff[ROWS*FFD];        // ff1 output
__device__ float g_qstar[BATCH*2*DIMM];
__device__ float g_h[BATCH*DIMM];
__device__ float g_c[BATCH*DIMM];
__device__ float g_h1[BATCH*DIMM];
__device__ float g_c1[BATCH*DIMM];
__device__ float g_feat[TT*5*DIMM];
__device__ float g_o1[TT*DIMM];
__device__ float g_o2[TT*ACT];
__device__ int   g_nr64;   // nonring is int64?
__device__ int   g_nb64;   // nrbidx is int64?
__device__ int   g_sz64;   // torsion_list_sizes is int64?

__device__ __forceinline__ float sigmoidf_(float x) { return 1.f / (1.f + expf(-x)); }

// ---------------- integer-dtype detection (deterministic, on-device) -------
// nonring: T*4=8064 values in [0, 32768). If stored int64, every odd int32
// word of the first 8064 words is the (zero) high half. If int32, the OR of
// 4032 random words is nonzero with probability 1 - 2^-60480.
// sizes: exactly arange(64). int32 -> word[1]==1; int64 -> word[1]==0.
__global__ void detect_dtypes(const int* __restrict__ nonring,
                              const int* __restrict__ nrbidx,
                              const int* __restrict__ sizes)
{
    if (threadIdx.x != 0 || blockIdx.x != 0) return;
    int any = 0;
    for (int i = 1; i < 4*TT; i += 2) any |= nonring[i];
    g_nr64 = (any == 0) ? 1 : 0;
    int any2 = 0;
    for (int i = 1; i < TT; i += 2) any2 |= nrbidx[i];
    g_nb64 = (any2 == 0) ? 1 : 0;
    g_sz64 = (sizes[1] == 0) ? 1 : 0;
}

// ---------------- generic NT SGEMM: C[M,N] = A[M,K] * B[N,K]^T + bias ------
template<int RELU>
__global__ __launch_bounds__(256) void gemm_nt(
    const float* __restrict__ A, const float* __restrict__ B,
    const float* __restrict__ bias, float* __restrict__ C,
    int M, int N, int K)
{
    __shared__ float As[16][64];
    __shared__ float Bs[16][64];
    const int t  = threadIdx.x;
    const int tx = t & 15, ty = t >> 4;
    const int bm = blockIdx.y * 64, bn = blockIdx.x * 64;

    const int lm = t >> 2;          // 0..63 : row within tile
    const int lk = (t & 3) * 4;     // 0,4,8,12 : k offset (float4)
    const bool aval = (bm + lm) < M;
    const bool bval = (bn + lm) < N;
    const float* Arow = A + (size_t)(bm + lm) * K + lk;
    const float* Brow = B + (size_t)(bn + lm) * K + lk;

    float acc[4][4];
    #pragma unroll
    for (int i = 0; i < 4; i++)
        #pragma unroll
        for (int j = 0; j < 4; j++) acc[i][j] = 0.f;

    for (int k0 = 0; k0 < K; k0 += 16) {
        float4 av = aval ? *(const float4*)(Arow + k0) : make_float4(0,0,0,0);
        float4 bv = bval ? *(const float4*)(Brow + k0) : make_float4(0,0,0,0);
        As[lk+0][lm] = av.x; As[lk+1][lm] = av.y; As[lk+2][lm] = av.z; As[lk+3][lm] = av.w;
        Bs[lk+0][lm] = bv.x; Bs[lk+1][lm] = bv.y; Bs[lk+2][lm] = bv.z; Bs[lk+3][lm] = bv.w;
        __syncthreads();
        #pragma unroll
        for (int kk = 0; kk < 16; kk++) {
            float4 a4 = *(const float4*)&As[kk][ty*4];
            float4 b4 = *(const float4*)&Bs[kk][tx*4];
            float ar[4] = {a4.x, a4.y, a4.z, a4.w};
            float br[4] = {b4.x, b4.y, b4.z, b4.w};
            #pragma unroll
            for (int i = 0; i < 4; i++)
                #pragma unroll
                for (int j = 0; j < 4; j++) acc[i][j] += ar[i]*br[j];
        }
        __syncthreads();
    }

    #pragma unroll
    for (int i = 0; i < 4; i++) {
        int m = bm + ty*4 + i;
        if (m >= M) continue;
        #pragma unroll
        for (int j = 0; j < 4; j++) {
            int n = bn + tx*4 + j;
            if (n >= N) continue;
            float v = acc[i][j] + bias[n];
            if (RELU) v = fmaxf(v, 0.f);
            C[(size_t)m * N + n] = v;
        }
    }
}

// ---------------- lin0: (32768,3) -> relu -> (32768,256) -------------------
__global__ void lin0_kernel(const float* __restrict__ data,
                            const float* __restrict__ w, const float* __restrict__ b)
{
    int r = blockIdx.x, d = threadIdx.x;
    float x0 = data[r*3+0], x1 = data[r*3+1], x2 = data[r*3+2];
    float v = b[d] + x0*w[d*3+0] + x1*w[d*3+1] + x2*w[d*3+2];
    g_x[(size_t)r*DIMM + d] = fmaxf(v, 0.f);
}

// ---------------- attention: per (atom n, head h) a 64x64x32 problem -------
__global__ __launch_bounds__(256) void attn_kernel(const float* __restrict__ qkv,
                                                   float* __restrict__ attn)
{
    int n = blockIdx.x >> 3, h = blockIdx.x & 7;
    __shared__ float Qs[64][33], Ks[64][33], Vs[64][33];
    __shared__ float St[64][65];
    int tid = threadIdx.x;

    for (int i = tid; i < 64*32; i += 256) {
        int s = i >> 5, d = i & 31;
        size_t base = ((size_t)s*ATOMS + n)*(3*DIMM) + h*DH + d;
        Qs[s][d] = qkv[base];
        Ks[s][d] = qkv[base + DIMM];
        Vs[s][d] = qkv[base + 2*DIMM];
    }
    __syncthreads();

    for (int p = tid; p < 64*64; p += 256) {
        int s = p >> 6, u = p & 63;
        float acc = 0.f;
        #pragma unroll
        for (int d = 0; d < 32; d++) acc += Qs[s][d]*Ks[u][d];
        St[s][u] = acc * 0.17677669529663687f;  // 1/sqrt(32)
    }
    __syncthreads();

    if (tid < 64) {
        float m = -1e30f;
        for (int u = 0; u < 64; u++) m = fmaxf(m, St[tid][u]);
        float sum = 0.f;
        for (int u = 0; u < 64; u++) { float e = expf(St[tid][u]-m); St[tid][u] = e; sum += e; }
        float inv = 1.f / sum;
        for (int u = 0; u < 64; u++) St[tid][u] *= inv;
    }
    __syncthreads();

    for (int p = tid; p < 64*32; p += 256) {
        int s = p >> 5, d = p & 31;
        float acc = 0.f;
        #pragma unroll
        for (int u = 0; u < 64; u++) acc += St[s][u]*Vs[u][d];
        attn[((size_t)s*ATOMS + n)*DIMM + h*DH + d] = acc;
    }
}

// ---------------- LayerNorm(x + res), in-place into x ----------------------
__global__ void ln_add(float* __restrict__ x, const float* __restrict__ r,
                       const float* __restrict__ g, const float* __restrict__ b)
{
    int row = blockIdx.x * 8 + threadIdx.y;
    int lane = threadIdx.x;
    size_t base = (size_t)row * DIMM;
    float v[8];
    float s = 0.f;
    #pragma unroll
    for (int i = 0; i < 8; i++) {
        v[i] = x[base + i*32 + lane] + r[base + i*32 + lane];
        s += v[i];
    }
    #pragma unroll
    for (int o = 16; o; o >>= 1) s += __shfl_xor_sync(0xffffffffu, s, o);
    float mean = s * (1.f/256.f);
    float vs = 0.f;
    #pragma unroll
    for (int i = 0; i < 8; i++) { float d = v[i]-mean; vs += d*d; }
    #pragma unroll
    for (int o = 16; o; o >>= 1) vs += __shfl_xor_sync(0xffffffffu, vs, o);
    float rstd = rsqrtf(vs * (1.f/256.f) + 1e-5f);
    #pragma unroll
    for (int i = 0; i < 8; i++)
        x[base + i*32 + lane] = (v[i]-mean)*rstd*g[i*32+lane] + b[i*32+lane];
}

// ---------------- LSTM step (torch gate order i,f,g,o), one block per b ----
__global__ __launch_bounds__(256) void lstm_step(
    const float* __restrict__ x,      // (B, 512)
    float* __restrict__ h, float* __restrict__ c,   // (B, 256)
    const float* __restrict__ wih, const float* __restrict__ whh,
    const float* __restrict__ bih, const float* __restrict__ bhh)
{
    int b = blockIdx.x, tid = threadIdx.x;
    __shared__ float xs[512], hs[256], gates[1024];
    for (int i = tid; i < 512; i += 256) xs[i] = x[b*512 + i];
    hs[tid] = h[b*256 + tid];
    __syncthreads();
    for (int gi = tid; gi < 1024; gi += 256) {
        const float* wr = wih + (size_t)gi*512;
        const float* hr = whh + (size_t)gi*256;
        float acc = bih[gi] + bhh[gi];
        for (int k = 0; k < 512; k++) acc += xs[k]*wr[k];
        for (int k = 0; k < 256; k++) acc += hs[k]*hr[k];
        gates[gi] = acc;
    }
    __syncthreads();
    float iv = gates[tid], fv = gates[256+tid], gv = gates[512+tid], ov = gates[768+tid];
    float cn = sigmoidf_(fv)*c[b*256+tid] + sigmoidf_(iv)*tanhf(gv);
    float hn = sigmoidf_(ov)*tanhf(cn);
    c[b*256+tid] = cn;
    h[b*256+tid] = hn;
}

// ---------------- Set2Set pooling: e = x3·h, softmax over atoms, r = a·x3 --
__global__ __launch_bounds__(256) void s2s_pool(const float* __restrict__ x3,
                                                const float* __restrict__ h,
                                                float* __restrict__ qstar)
{
    int b = blockIdx.x, tid = threadIdx.x;
    int lane = tid & 31, wid = tid >> 5;
    __shared__ float hs[256];
    __shared__ float w[512];
    __shared__ float rbuf[256];
    hs[tid] = h[b*256 + tid];
    __syncthreads();
    for (int a = wid; a < 512; a += 8) {
        const float* row = x3 + ((size_t)b*ATOMS + a)*DIMM;
        float p = 0.f;
        #pragma unroll
        for (int i = 0; i < 8; i++) p += row[lane + i*32]*hs[lane + i*32];
        #pragma unroll
        for (int o = 16; o; o >>= 1) p += __shfl_xor_sync(0xffffffffu, p, o);
        if (lane == 0) w[a] = p;
    }
    __syncthreads();
    rbuf[tid] = fmaxf(w[tid], w[tid+256]);
    __syncthreads();
    for (int s = 128; s; s >>= 1) { if (tid < s) rbuf[tid] = fmaxf(rbuf[tid], rbuf[tid+s]); __syncthreads(); }
    float mx = rbuf[0];
    __syncthreads();
    float e1 = expf(w[tid]-mx), e2 = expf(w[tid+256]-mx);
    w[tid] = e1; w[tid+256] = e2;
    rbuf[tid] = e1 + e2;
    __syncthreads();
    for (int s = 128; s; s >>= 1) { if (tid < s) rbuf[tid] += rbuf[tid+s]; __syncthreads(); }
    float inv = 1.f / rbuf[0];
    float acc = 0.f;
    for (int a = 0; a < 512; a++) acc += w[a]*x3[((size_t)b*ATOMS + a)*DIMM + tid];
    qstar[b*512 + tid]       = hs[tid];
    qstar[b*512 + 256 + tid] = acc * inv;
}

// ---------------- feat gather: replicates transpose((2,1,0)).reshape(T,1280)
__global__ void gather_feat(const float* __restrict__ out_flat,
                            const float* __restrict__ h1,
                            const void* __restrict__ nonring_raw,
                            const void* __restrict__ nrbidx_raw,
                            float* __restrict__ feat)
{
    int idx = blockIdx.x * blockDim.x + threadIdx.x;
    if (idx >= TT*5*DIMM) return;
    int d   = idx / (5*TT);         // flat index = d*(T*5) + t*5 + s
    int rem = idx % (5*TT);
    int tt  = rem / 5;
    int s   = rem % 5;
    float v;
    if (s == 0) {
        int bb = g_nb64 ? (int)((const long long*)nrbidx_raw)[tt]
                        : ((const int*)nrbidx_raw)[tt];
        v = h1[bb*DIMM + d];
    } else {
        int j = (s-1)*TT + tt;      // flat (T,4) row-major, reshaped (4,T)
        int src = g_nr64 ? (int)((const long long*)nonring_raw)[j]
                         : ((const int*)nonring_raw)[j];
        v = out_flat[(size_t)src*DIMM + d];
    }
    feat[idx] = v;
}

// ---------------- lin2: (T,256) -> (T,6) -----------------------------------
__global__ void lin2_kernel(const float* __restrict__ o1, const float* __restrict__ w,
                            const float* __restrict__ b, float* __restrict__ o2)
{
    int idx = blockIdx.x * blockDim.x + threadIdx.x;
    if (idx >= TT*ACT) return;
    int tt = idx / ACT, j = idx % ACT;
    const float* row = o1 + (size_t)tt*DIMM;
    const float* wr  = w + (size_t)j*DIMM;
    float acc = b[j];
    for (int k = 0; k < DIMM; k++) acc += row[k]*wr[k];
    o2[idx] = acc;
}

// ---------------- scatter into padded logits --------------------------------
__global__ void scatter_out(const float* __restrict__ o2,
                            const void* __restrict__ sizes_raw,
                            float* __restrict__ out)
{
    int tt = blockIdx.x * blockDim.x + threadIdx.x;
    if (tt >= TT) return;
    const long long* s64 = (const long long*)sizes_raw;
    const int*       s32 = (const int*)sizes_raw;
    int is64 = g_sz64;
    long long off = 0; int b = 0;
    while (b < BATCH-1) {
        long long sz = is64 ? s64[b] : (long long)s32[b];
        long long nx = off + sz;
        if (tt < nx) break;
        off = nx; b++;
    }
    int pos = tt - (int)off;
    for (int k = 0; k < ACT; k++)
        out[((size_t)b*MAXS + pos)*ACT + k] = o2[tt*ACT + k];
}

__global__ void fill_kernel(float* __restrict__ p, int n, float v)
{
    int i = blockIdx.x * blockDim.x + threadIdx.x;
    if (i < n) p[i] = v;
}

__global__ void copy_kernel(float* __restrict__ dst, const float* __restrict__ src, int n)
{
    int i = blockIdx.x * blockDim.x + threadIdx.x;
    if (i < n) dst[i] = src[i];
}

// ---------------------------------------------------------------------------
extern "C" void kernel_launch(void* const* d_in, const int* in_sizes, int n_in,
                              void* d_out, int out_size)
{
    const float* data    = (const float*)d_in[0];
    const void*  nonring = d_in[1];
    const void*  nrbidx  = d_in[2];
    const void*  sizes   = d_in[3];
    const float* lin0_w = (const float*)d_in[4];
    const float* lin0_b = (const float*)d_in[5];
    const float* qkv_w  = (const float*)d_in[6];
    const float* qkv_b  = (const float*)d_in[7];
    const float* out_w  = (const float*)d_in[8];
    const float* out_b  = (const float*)d_in[9];
    const float* ff1_w  = (const float*)d_in[10];
    const float* ff1_b  = (const float*)d_in[11];
    const float* ff2_w  = (const float*)d_in[12];
    const float* ff2_b  = (const float*)d_in[13];
    const float* ln1_g  = (const float*)d_in[14];
    const float* ln1_b  = (const float*)d_in[15];
    const float* ln2_g  = (const float*)d_in[16];
    const float* ln2_b  = (const float*)d_in[17];
    const float* s2s_wih = (const float*)d_in[18];
    const float* s2s_whh = (const float*)d_in[19];
    const float* s2s_bih = (const float*)d_in[20];
    const float* s2s_bhh = (const float*)d_in[21];
    const float* mem_wih = (const float*)d_in[22];
    const float* mem_whh = (const float*)d_in[23];
    const float* mem_bih = (const float*)d_in[24];
    const float* mem_bhh = (const float*)d_in[25];
    const float* lin1_w  = (const float*)d_in[26];
    const float* lin1_b  = (const float*)d_in[27];
    const float* lin2_w  = (const float*)d_in[28];
    const float* lin2_b  = (const float*)d_in[29];
    float* out = (float*)d_out;

    float *px, *pqkv, *pattn, *ptmp, *pff, *pqstar, *ph, *pc, *ph1, *pc1, *pfeat, *po1, *po2;
    cudaGetSymbolAddress((void**)&px,    g_x);
    cudaGetSymbolAddress((void**)&pqkv,  g_qkv);
    cudaGetSymbolAddress((void**)&pattn, g_attn);
    cudaGetSymbolAddress((void**)&ptmp,  g_tmp);
    cudaGetSymbolAddress((void**)&pff,   g_ff);
    cudaGetSymbolAddress((void**)&pqstar,g_qstar);
    cudaGetSymbolAddress((void**)&ph,    g_h);
    cudaGetSymbolAddress((void**)&pc,    g_c);
    cudaGetSymbolAddress((void**)&ph1,   g_h1);
    cudaGetSymbolAddress((void**)&pc1,   g_c1);
    cudaGetSymbolAddress((void**)&pfeat, g_feat);
    cudaGetSymbolAddress((void**)&po1,   g_o1);
    cudaGetSymbolAddress((void**)&po2,   g_o2);

    // 0. integer dtype detection (x64 on/off produces int64/int32 inputs)
    detect_dtypes<<<1, 1>>>((const int*)nonring, (const int*)nrbidx, (const int*)sizes);

    // 1. lin0 + relu
    lin0_kernel<<<ROWS, DIMM>>>(data, lin0_w, lin0_b);

    // 2. encoder layers
    for (int l = 0; l < NLAYERS; l++) {
        const float* wq  = qkv_w + (size_t)l*3*DIMM*DIMM;
        const float* bq  = qkv_b + (size_t)l*3*DIMM;
        const float* wo  = out_w + (size_t)l*DIMM*DIMM;
        const float* bo  = out_b + (size_t)l*DIMM;
        const float* w1  = ff1_w + (size_t)l*FFD*DIMM;
        const float* b1  = ff1_b + (size_t)l*FFD;
        const float* w2  = ff2_w + (size_t)l*DIMM*FFD;
        const float* b2  = ff2_b + (size_t)l*DIMM;

        gemm_nt<0><<<dim3(3*DIMM/64, ROWS/64), 256>>>(px, wq, bq, pqkv, ROWS, 3*DIMM, DIMM);
        attn_kernel<<<ATOMS*NHEADS, 256>>>(pqkv, pattn);
        gemm_nt<0><<<dim3(DIMM/64, ROWS/64), 256>>>(pattn, wo, bo, ptmp, ROWS, DIMM, DIMM);
        ln_add<<<ROWS/8, dim3(32,8)>>>(px, ptmp, ln1_g + l*DIMM, ln1_b + l*DIMM);
        gemm_nt<1><<<dim3(FFD/64, ROWS/64), 256>>>(px, w1, b1, pff, ROWS, FFD, DIMM);
        gemm_nt<0><<<dim3(DIMM/64, ROWS/64), 256>>>(pff, w2, b2, ptmp, ROWS, DIMM, FFD);
        ln_add<<<ROWS/8, dim3(32,8)>>>(px, ptmp, ln2_g + l*DIMM, ln2_b + l*DIMM);
    }

    // 3. Set2Set
    fill_kernel<<<(BATCH*2*DIMM+255)/256, 256>>>(pqstar, BATCH*2*DIMM, 0.f);
    fill_kernel<<<(BATCH*DIMM+255)/256, 256>>>(ph, BATCH*DIMM, 0.f);
    fill_kernel<<<(BATCH*DIMM+255)/256, 256>>>(pc, BATCH*DIMM, 0.f);
    for (int s = 0; s < 6; s++) {
        lstm_step<<<BATCH, 256>>>(pqstar, ph, pc, s2s_wih, s2s_whh, s2s_bih, s2s_bhh);
        s2s_pool<<<BATCH, 256>>>(px, ph, pqstar);
    }

    // 4. memory LSTM (zero init states)
    fill_kernel<<<(BATCH*DIMM+255)/256, 256>>>(ph1, BATCH*DIMM, 0.f);
    fill_kernel<<<(BATCH*DIMM+255)/256, 256>>>(pc1, BATCH*DIMM, 0.f);
    lstm_step<<<BATCH, 256>>>(pqstar, ph1, pc1, mem_wih, mem_whh, mem_bih, mem_bhh);

    // 5. feat gather + lin1 + lin2
    gather_feat<<<(TT*5*DIMM + 255)/256, 256>>>(px, ph1, nonring, nrbidx, pfeat);
    gemm_nt<1><<<dim3(DIMM/64, (TT+63)/64), 256>>>(pfeat, lin1_w, lin1_b, po1, TT, DIMM, 5*DIMM);
    lin2_kernel<<<(TT*ACT + 255)/256, 256>>>(po1, lin2_w, lin2_b, po2);

    // 6. outputs: [logit (64*63*6) | h1 (64*256) | c1 (64*256)]
    fill_kernel<<<(BATCH*MAXS*ACT + 255)/256, 256>>>(out, BATCH*MAXS*ACT, 0.f);
    scatter_out<<<(TT + 255)/256, 256>>>(po2, sizes, out);
    copy_kernel<<<(BATCH*DIMM + 255)/256, 256>>>(out + BATCH*MAXS*ACT, ph1, BATCH*DIMM);
    copy_kernel<<<(BATCH*DIMM + 255)/256, 256>>>(out + BATCH*MAXS*ACT + BATCH*DIMM, pc1, BATCH*DIMM);
}

// round 8
// speedup vs baseline: 1.9018x; 1.9018x over previous
#include <cuda_runtime.h>
#include <cuda_bf16.h>
#include <math.h>
#include <stdint.h>

#define DIMM 256
#define BATCH 64
#define ATOMS 512
#define ROWS (BATCH*ATOMS)   /* 32768 */
#define NLAYERS 6
#define FFD 2048
#define TT 2016
#define ACT 6
#define MAXS 63
#define NHEADS 8
#define DH 32

typedef __nv_bfloat16 bf16;

// ---------------- scratch (device globals; no allocation allowed) ----------
__device__ float g_x[ROWS*DIMM];          // residual stream fp32
__device__ bf16  g_xh[ROWS*DIMM];         // x split hi
__device__ bf16  g_xl[ROWS*DIMM];         // x split lo
__device__ float g_qkv[ROWS*3*DIMM];      // qkv projections (fp32, attn consumes)
__device__ bf16  g_ah[ROWS*DIMM];         // attn out split hi
__device__ bf16  g_al[ROWS*DIMM];         // attn out split lo
__device__ float g_tmp[ROWS*DIMM];        // proj / ff2 output fp32
__device__ bf16  g_fh[ROWS*FFD];          // ff1 out split hi
__device__ bf16  g_fl[ROWS*FFD];          // ff1 out split lo
__device__ bf16  g_wqh[NLAYERS*3*DIMM*DIMM], g_wql[NLAYERS*3*DIMM*DIMM];
__device__ bf16  g_woh[NLAYERS*DIMM*DIMM],   g_wol[NLAYERS*DIMM*DIMM];
__device__ bf16  g_w1h[NLAYERS*FFD*DIMM],    g_w1l[NLAYERS*FFD*DIMM];
__device__ bf16  g_w2h[NLAYERS*DIMM*FFD],    g_w2l[NLAYERS*DIMM*FFD];
__device__ float g_qstar[BATCH*2*DIMM];
__device__ float g_h[BATCH*DIMM];
__device__ float g_c[BATCH*DIMM];
__device__ float g_h1[BATCH*DIMM];
__device__ float g_c1[BATCH*DIMM];
__device__ float g_feat[TT*5*DIMM];
__device__ float g_o1[TT*DIMM];
__device__ float g_o2[TT*ACT];
__device__ int   g_nr64, g_nb64, g_sz64;

__device__ __forceinline__ float sigmoidf_(float x) { return 1.f / (1.f + expf(-x)); }

// ======================= split helpers =====================================
__device__ __forceinline__ void split_bf16(float v, bf16& h, bf16& l) {
    h = __float2bfloat16_rn(v);
    l = __float2bfloat16_rn(v - __bfloat162float(h));
}
__global__ void split_kernel(const float* __restrict__ s, bf16* __restrict__ hi,
                             bf16* __restrict__ lo, int n)
{
    int i = blockIdx.x * blockDim.x + threadIdx.x;
    if (i >= n) return;
    float v = s[i];
    bf16 h, l; split_bf16(v, h, l);
    hi[i] = h; lo[i] = l;
}

// ---------------- integer-dtype detection (deterministic, on-device) -------
__global__ void detect_dtypes(const int* __restrict__ nonring,
                              const int* __restrict__ nrbidx,
                              const int* __restrict__ sizes)
{
    if (threadIdx.x != 0 || blockIdx.x != 0) return;
    int any = 0;
    for (int i = 1; i < 4*TT; i += 2) any |= nonring[i];
    g_nr64 = (any == 0) ? 1 : 0;
    int any2 = 0;
    for (int i = 1; i < TT; i += 2) any2 |= nrbidx[i];
    g_nb64 = (any2 == 0) ? 1 : 0;
    g_sz64 = (sizes[1] == 0) ? 1 : 0;
}

// ======================= mma.sync bf16-split GEMM ==========================
// C[M,N] = A[M,K] * B[N,K]^T (+bias). A,B as bf16 hi/lo splits; split product
// AhBh + AhBl + AlBh in fp32 accumulators (drops ~2^-18 AlBl term).
// mma.sync.aligned.m16n8k16.row.col: A row-major [M,K], B "col" = [N,K] row-
// major (exactly our layout). Tiles: BM=128, BN=128, BK=32; 8 warps (2x4),
// warp tile 64x32. Smem rows padded to LDA=40 bf16 -> conflict-free frags.
#define BM 128
#define BN 128
#define BKS 32
#define LDA 40                       /* bf16 elements per smem row */
#define TILE_E (128*LDA)             /* 5120 bf16 per matrix tile */
#define STAGE_E (4*TILE_E)           /* Ah|Al|Bh|Bl */
#define GSM_BYTES (2*STAGE_E*2)      /* 81920 B, double buffered */

#define MMA16816(d, a, b) \
    asm volatile("mma.sync.aligned.m16n8k16.row.col.f32.bf16.bf16.f32 " \
        "{%0,%1,%2,%3}, {%4,%5,%6,%7}, {%8,%9}, {%0,%1,%2,%3};" \
        : "+f"((d)[0]), "+f"((d)[1]), "+f"((d)[2]), "+f"((d)[3]) \
        : "r"((a)[0]), "r"((a)[1]), "r"((a)[2]), "r"((a)[3]), \
          "r"((b)[0]), "r"((b)[1]))

template<int RELU, int SPLITOUT>
__global__ __launch_bounds__(256) void gemm_mma(
    const bf16* __restrict__ Ah, const bf16* __restrict__ Al,
    const bf16* __restrict__ Bh, const bf16* __restrict__ Bl,
    const float* __restrict__ bias,
    float* __restrict__ Cf, bf16* __restrict__ Ch, bf16* __restrict__ Cl,
    int M, int N, int K)
{
    extern __shared__ bf16 sm[];
    const int tid  = threadIdx.x;
    const int lane = tid & 31, wid = tid >> 5;
    const int wm = wid >> 2, wn = wid & 3;        // 2 x 4 warp grid
    const int bm = blockIdx.y * BM, bn = blockIdx.x * BN;
    const int g  = lane >> 2, tq = lane & 3;

    float acc[4][4][4];
    #pragma unroll
    for (int mt = 0; mt < 4; mt++)
        #pragma unroll
        for (int nt = 0; nt < 4; nt++)
            #pragma unroll
            for (int r = 0; r < 4; r++) acc[mt][nt][r] = 0.f;

    const int chunks = K / BKS;
    uint4 ld[8];

    // ---- preload chunk 0 ----
    {
        const int kof = 0;
        #pragma unroll
        for (int t = 0; t < 2; t++) {
            int i = tid + t*256;
            int row = i >> 2, q = (i & 3) * 8;
            ld[t*4+0] = *(const uint4*)(Ah + (size_t)(bm+row)*K + kof + q);
            ld[t*4+1] = *(const uint4*)(Al + (size_t)(bm+row)*K + kof + q);
            ld[t*4+2] = *(const uint4*)(Bh + (size_t)(bn+row)*K + kof + q);
            ld[t*4+3] = *(const uint4*)(Bl + (size_t)(bn+row)*K + kof + q);
        }
        bf16* st = sm;
        #pragma unroll
        for (int t = 0; t < 2; t++) {
            int i = tid + t*256;
            int row = i >> 2, q = (i & 3) * 8;
            *(uint4*)(st + 0*TILE_E + row*LDA + q) = ld[t*4+0];
            *(uint4*)(st + 1*TILE_E + row*LDA + q) = ld[t*4+1];
            *(uint4*)(st + 2*TILE_E + row*LDA + q) = ld[t*4+2];
            *(uint4*)(st + 3*TILE_E + row*LDA + q) = ld[t*4+3];
        }
    }
    __syncthreads();

    for (int ch = 0; ch < chunks; ch++) {
        // prefetch next chunk into registers (overlaps with compute)
        if (ch + 1 < chunks) {
            const int kof = (ch + 1) * BKS;
            #pragma unroll
            for (int t = 0; t < 2; t++) {
                int i = tid + t*256;
                int row = i >> 2, q = (i & 3) * 8;
                ld[t*4+0] = *(const uint4*)(Ah + (size_t)(bm+row)*K + kof + q);
                ld[t*4+1] = *(const uint4*)(Al + (size_t)(bm+row)*K + kof + q);
                ld[t*4+2] = *(const uint4*)(Bh + (size_t)(bn+row)*K + kof + q);
                ld[t*4+3] = *(const uint4*)(Bl + (size_t)(bn+row)*K + kof + q);
            }
        }
        // compute on current buffer
        {
            const bf16* tAh = sm + (ch & 1) * STAGE_E;
            const bf16* tAl = tAh + TILE_E;
            const bf16* tBh = tAh + 2*TILE_E;
            const bf16* tBl = tAh + 3*TILE_E;
            #pragma unroll
            for (int ks = 0; ks < 2; ks++) {
                const int kb = ks * 16;
                const int c0 = kb + tq*2;
                uint32_t ah[4][4], al[4][4];
                #pragma unroll
                for (int mt = 0; mt < 4; mt++) {
                    int r0 = wm*64 + mt*16 + g;
                    ah[mt][0] = *(const uint32_t*)(tAh + r0*LDA + c0);
                    ah[mt][1] = *(const uint32_t*)(tAh + (r0+8)*LDA + c0);
                    ah[mt][2] = *(const uint32_t*)(tAh + r0*LDA + c0 + 8);
                    ah[mt][3] = *(const uint32_t*)(tAh + (r0+8)*LDA + c0 + 8);
                    al[mt][0] = *(const uint32_t*)(tAl + r0*LDA + c0);
                    al[mt][1] = *(const uint32_t*)(tAl + (r0+8)*LDA + c0);
                    al[mt][2] = *(const uint32_t*)(tAl + r0*LDA + c0 + 8);
                    al[mt][3] = *(const uint32_t*)(tAl + (r0+8)*LDA + c0 + 8);
                }
                uint32_t bh[4][2], bl[4][2];
                #pragma unroll
                for (int nt = 0; nt < 4; nt++) {
                    int n0 = wn*32 + nt*8 + g;
                    bh[nt][0] = *(const uint32_t*)(tBh + n0*LDA + c0);
                    bh[nt][1] = *(const uint32_t*)(tBh + n0*LDA + c0 + 8);
                    bl[nt][0] = *(const uint32_t*)(tBl + n0*LDA + c0);
                    bl[nt][1] = *(const uint32_t*)(tBl + n0*LDA + c0 + 8);
                }
                #pragma unroll
                for (int mt = 0; mt < 4; mt++)
                    #pragma unroll
                    for (int nt = 0; nt < 4; nt++) {
                        MMA16816(acc[mt][nt], ah[mt], bh[nt]);
                        MMA16816(acc[mt][nt], ah[mt], bl[nt]);
                        MMA16816(acc[mt][nt], al[mt], bh[nt]);
                    }
            }
        }
        // store prefetched chunk into the other buffer
        if (ch + 1 < chunks) {
            bf16* st = sm + ((ch + 1) & 1) * STAGE_E;
            #pragma unroll
            for (int t = 0; t < 2; t++) {
                int i = tid + t*256;
                int row = i >> 2, q = (i & 3) * 8;
                *(uint4*)(st + 0*TILE_E + row*LDA + q) = ld[t*4+0];
                *(uint4*)(st + 1*TILE_E + row*LDA + q) = ld[t*4+1];
                *(uint4*)(st + 2*TILE_E + row*LDA + q) = ld[t*4+2];
                *(uint4*)(st + 3*TILE_E + row*LDA + q) = ld[t*4+3];
            }
            __syncthreads();
        }
    }

    // ---- epilogue: bias (+relu), fp32 or bf16-split output ----
    #pragma unroll
    for (int mt = 0; mt < 4; mt++)
        #pragma unroll
        for (int nt = 0; nt < 4; nt++) {
            int row = bm + wm*64 + mt*16 + g;
            int col = bn + wn*32 + nt*8 + tq*2;
            float b0 = bias[col], b1 = bias[col+1];
            float v0 = acc[mt][nt][0] + b0, v1 = acc[mt][nt][1] + b1;
            float v2 = acc[mt][nt][2] + b0, v3 = acc[mt][nt][3] + b1;
            if (RELU) {
                v0 = fmaxf(v0, 0.f); v1 = fmaxf(v1, 0.f);
                v2 = fmaxf(v2, 0.f); v3 = fmaxf(v3, 0.f);
            }
            if (SPLITOUT) {
                bf16 h0,l0,h1,l1,h2,l2,h3,l3;
                split_bf16(v0,h0,l0); split_bf16(v1,h1,l1);
                split_bf16(v2,h2,l2); split_bf16(v3,h3,l3);
                uint32_t ph01 = (uint32_t)__bfloat16_as_ushort(h1) << 16 | __bfloat16_as_ushort(h0);
                uint32_t pl01 = (uint32_t)__bfloat16_as_ushort(l1) << 16 | __bfloat16_as_ushort(l0);
                uint32_t ph23 = (uint32_t)__bfloat16_as_ushort(h3) << 16 | __bfloat16_as_ushort(h2);
                uint32_t pl23 = (uint32_t)__bfloat16_as_ushort(l3) << 16 | __bfloat16_as_ushort(l2);
                *(uint32_t*)(Ch + (size_t)row*N + col)     = ph01;
                *(uint32_t*)(Cl + (size_t)row*N + col)     = pl01;
                *(uint32_t*)(Ch + (size_t)(row+8)*N + col) = ph23;
                *(uint32_t*)(Cl + (size_t)(row+8)*N + col) = pl23;
            } else {
                *(float2*)(Cf + (size_t)row*N + col)     = make_float2(v0, v1);
                *(float2*)(Cf + (size_t)(row+8)*N + col) = make_float2(v2, v3);
            }
        }
}

// ---------------- generic NT SGEMM (kept for lin1, fp32) -------------------
template<int RELU>
__global__ __launch_bounds__(256) void gemm_nt(
    const float* __restrict__ A, const float* __restrict__ B,
    const float* __restrict__ bias, float* __restrict__ C,
    int M, int N, int K)
{
    __shared__ float As[16][64];
    __shared__ float Bs[16][64];
    const int t  = threadIdx.x;
    const int tx = t & 15, ty = t >> 4;
    const int bm = blockIdx.y * 64, bn = blockIdx.x * 64;
    const int lm = t >> 2;
    const int lk = (t & 3) * 4;
    const bool aval = (bm + lm) < M;
    const bool bval = (bn + lm) < N;
    const float* Arow = A + (size_t)(bm + lm) * K + lk;
    const float* Brow = B + (size_t)(bn + lm) * K + lk;

    float acc[4][4];
    #pragma unroll
    for (int i = 0; i < 4; i++)
        #pragma unroll
        for (int j = 0; j < 4; j++) acc[i][j] = 0.f;

    for (int k0 = 0; k0 < K; k0 += 16) {
        float4 av = aval ? *(const float4*)(Arow + k0) : make_float4(0,0,0,0);
        float4 bv = bval ? *(const float4*)(Brow + k0) : make_float4(0,0,0,0);
        As[lk+0][lm] = av.x; As[lk+1][lm] = av.y; As[lk+2][lm] = av.z; As[lk+3][lm] = av.w;
        Bs[lk+0][lm] = bv.x; Bs[lk+1][lm] = bv.y; Bs[lk+2][lm] = bv.z; Bs[lk+3][lm] = bv.w;
        __syncthreads();
        #pragma unroll
        for (int kk = 0; kk < 16; kk++) {
            float4 a4 = *(const float4*)&As[kk][ty*4];
            float4 b4 = *(const float4*)&Bs[kk][tx*4];
            float ar[4] = {a4.x, a4.y, a4.z, a4.w};
            float br[4] = {b4.x, b4.y, b4.z, b4.w};
            #pragma unroll
            for (int i = 0; i < 4; i++)
                #pragma unroll
                for (int j = 0; j < 4; j++) acc[i][j] += ar[i]*br[j];
        }
        __syncthreads();
    }
    #pragma unroll
    for (int i = 0; i < 4; i++) {
        int m = bm + ty*4 + i;
        if (m >= M) continue;
        #pragma unroll
        for (int j = 0; j < 4; j++) {
            int n = bn + tx*4 + j;
            if (n >= N) continue;
            float v = acc[i][j] + bias[n];
            if (RELU) v = fmaxf(v, 0.f);
            C[(size_t)m * N + n] = v;
        }
    }
}

// ---------------- lin0: (32768,3) -> relu -> x + split ---------------------
__global__ void lin0_kernel(const float* __restrict__ data,
                            const float* __restrict__ w, const float* __restrict__ b)
{
    int r = blockIdx.x, d = threadIdx.x;
    float x0 = data[r*3+0], x1 = data[r*3+1], x2 = data[r*3+2];
    float v = b[d] + x0*w[d*3+0] + x1*w[d*3+1] + x2*w[d*3+2];
    v = fmaxf(v, 0.f);
    size_t o = (size_t)r*DIMM + d;
    g_x[o] = v;
    bf16 h, l; split_bf16(v, h, l);
    g_xh[o] = h; g_xl[o] = l;
}

// ---------------- attention: per (atom n, head h) a 64x64x32 problem -------
__global__ __launch_bounds__(256) void attn_kernel(const float* __restrict__ qkv)
{
    int n = blockIdx.x >> 3, h = blockIdx.x & 7;
    __shared__ float Qs[64][33], Ks[64][33], Vs[64][33];
    __shared__ float St[64][65];
    int tid = threadIdx.x;

    for (int i = tid; i < 64*32; i += 256) {
        int s = i >> 5, d = i & 31;
        size_t base = ((size_t)s*ATOMS + n)*(3*DIMM) + h*DH + d;
        Qs[s][d] = qkv[base];
        Ks[s][d] = qkv[base + DIMM];
        Vs[s][d] = qkv[base + 2*DIMM];
    }
    __syncthreads();

    for (int p = tid; p < 64*64; p += 256) {
        int s = p >> 6, u = p & 63;
        float acc = 0.f;
        #pragma unroll
        for (int d = 0; d < 32; d++) acc += Qs[s][d]*Ks[u][d];
        St[s][u] = acc * 0.17677669529663687f;
    }
    __syncthreads();

    if (tid < 64) {
        float m = -1e30f;
        for (int u = 0; u < 64; u++) m = fmaxf(m, St[tid][u]);
        float sum = 0.f;
        for (int u = 0; u < 64; u++) { float e = expf(St[tid][u]-m); St[tid][u] = e; sum += e; }
        float inv = 1.f / sum;
        for (int u = 0; u < 64; u++) St[tid][u] *= inv;
    }
    __syncthreads();

    for (int p = tid; p < 64*32; p += 256) {
        int s = p >> 5, d = p & 31;
        float acc = 0.f;
        #pragma unroll
        for (int u = 0; u < 64; u++) acc += St[s][u]*Vs[u][d];
        size_t o = ((size_t)s*ATOMS + n)*DIMM + h*DH + d;
        bf16 hh, ll; split_bf16(acc, hh, ll);
        g_ah[o] = hh; g_al[o] = ll;
    }
}

// ---------------- LayerNorm(x + res) -> x fp32 + split ---------------------
__global__ void ln_add(float* __restrict__ x, const float* __restrict__ r,
                       const float* __restrict__ g, const float* __restrict__ b)
{
    int row = blockIdx.x * 8 + threadIdx.y;
    int lane = threadIdx.x;
    size_t base = (size_t)row * DIMM;
    float v[8];
    float s = 0.f;
    #pragma unroll
    for (int i = 0; i < 8; i++) {
        v[i] = x[base + i*32 + lane] + r[base + i*32 + lane];
        s += v[i];
    }
    #pragma unroll
    for (int o = 16; o; o >>= 1) s += __shfl_xor_sync(0xffffffffu, s, o);
    float mean = s * (1.f/256.f);
    float vs = 0.f;
    #pragma unroll
    for (int i = 0; i < 8; i++) { float d = v[i]-mean; vs += d*d; }
    #pragma unroll
    for (int o = 16; o; o >>= 1) vs += __shfl_xor_sync(0xffffffffu, vs, o);
    float rstd = rsqrtf(vs * (1.f/256.f) + 1e-5f);
    #pragma unroll
    for (int i = 0; i < 8; i++) {
        float val = (v[i]-mean)*rstd*g[i*32+lane] + b[i*32+lane];
        size_t o = base + i*32 + lane;
        x[o] = val;
        bf16 hh, ll; split_bf16(val, hh, ll);
        g_xh[o] = hh; g_xl[o] = ll;
    }
}

// ---------------- LSTM step (torch gate order i,f,g,o) ---------------------
__global__ __launch_bounds__(256) void lstm_step(
    const float* __restrict__ x,
    float* __restrict__ h, float* __restrict__ c,
    const float* __restrict__ wih, const float* __restrict__ whh,
    const float* __restrict__ bih, const float* __restrict__ bhh)
{
    int b = blockIdx.x, tid = threadIdx.x;
    __shared__ float xs[512], hs[256], gates[1024];
    for (int i = tid; i < 512; i += 256) xs[i] = x[b*512 + i];
    hs[tid] = h[b*256 + tid];
    __syncthreads();
    for (int gi = tid; gi < 1024; gi += 256) {
        const float* wr = wih + (size_t)gi*512;
        const float* hr = whh + (size_t)gi*256;
        float acc = bih[gi] + bhh[gi];
        for (int k = 0; k < 512; k++) acc += xs[k]*wr[k];
        for (int k = 0; k < 256; k++) acc += hs[k]*hr[k];
        gates[gi] = acc;
    }
    __syncthreads();
    float iv = gates[tid], fv = gates[256+tid], gv = gates[512+tid], ov = gates[768+tid];
    float cn = sigmoidf_(fv)*c[b*256+tid] + sigmoidf_(iv)*tanhf(gv);
    float hn = sigmoidf_(ov)*tanhf(cn);
    c[b*256+tid] = cn;
    h[b*256+tid] = hn;
}

// ---------------- Set2Set pooling ------------------------------------------
__global__ __launch_bounds__(256) void s2s_pool(const float* __restrict__ x3,
                                                const float* __restrict__ h,
                                                float* __restrict__ qstar)
{
    int b = blockIdx.x, tid = threadIdx.x;
    int lane = tid & 31, wid = tid >> 5;
    __shared__ float hs[256];
    __shared__ float w[512];
    __shared__ float rbuf[256];
    hs[tid] = h[b*256 + tid];
    __syncthreads();
    for (int a = wid; a < 512; a += 8) {
        const float* row = x3 + ((size_t)b*ATOMS + a)*DIMM;
        float p = 0.f;
        #pragma unroll
        for (int i = 0; i < 8; i++) p += row[lane + i*32]*hs[lane + i*32];
        #pragma unroll
        for (int o = 16; o; o >>= 1) p += __shfl_xor_sync(0xffffffffu, p, o);
        if (lane == 0) w[a] = p;
    }
    __syncthreads();
    rbuf[tid] = fmaxf(w[tid], w[tid+256]);
    __syncthreads();
    for (int s = 128; s; s >>= 1) { if (tid < s) rbuf[tid] = fmaxf(rbuf[tid], rbuf[tid+s]); __syncthreads(); }
    float mx = rbuf[0];
    __syncthreads();
    float e1 = expf(w[tid]-mx), e2 = expf(w[tid+256]-mx);
    w[tid] = e1; w[tid+256] = e2;
    rbuf[tid] = e1 + e2;
    __syncthreads();
    for (int s = 128; s; s >>= 1) { if (tid < s) rbuf[tid] += rbuf[tid+s]; __syncthreads(); }
    float inv = 1.f / rbuf[0];
    float acc = 0.f;
    for (int a = 0; a < 512; a++) acc += w[a]*x3[((size_t)b*ATOMS + a)*DIMM + tid];
    qstar[b*512 + tid]       = hs[tid];
    qstar[b*512 + 256 + tid] = acc * inv;
}

// ---------------- feat gather ----------------------------------------------
__global__ void gather_feat(const float* __restrict__ out_flat,
                            const float* __restrict__ h1,
                            const void* __restrict__ nonring_raw,
                            const void* __restrict__ nrbidx_raw,
                            float* __restrict__ feat)
{
    int idx = blockIdx.x * blockDim.x + threadIdx.x;
    if (idx >= TT*5*DIMM) return;
    int d   = idx / (5*TT);
    int rem = idx % (5*TT);
    int tt  = rem / 5;
    int s   = rem % 5;
    float v;
    if (s == 0) {
        int bb = g_nb64 ? (int)((const long long*)nrbidx_raw)[tt]
                        : ((const int*)nrbidx_raw)[tt];
        v = h1[bb*DIMM + d];
    } else {
        int j = (s-1)*TT + tt;
        int src = g_nr64 ? (int)((const long long*)nonring_raw)[j]
                         : ((const int*)nonring_raw)[j];
        v = out_flat[(size_t)src*DIMM + d];
    }
    feat[idx] = v;
}

// ---------------- lin2 ------------------------------------------------------
__global__ void lin2_kernel(const float* __restrict__ o1, const float* __restrict__ w,
                            const float* __restrict__ b, float* __restrict__ o2)
{
    int idx = blockIdx.x * blockDim.x + threadIdx.x;
    if (idx >= TT*ACT) return;
    int tt = idx / ACT, j = idx % ACT;
    const float* row = o1 + (size_t)tt*DIMM;
    const float* wr  = w + (size_t)j*DIMM;
    float acc = b[j];
    for (int k = 0; k < DIMM; k++) acc += row[k]*wr[k];
    o2[idx] = acc;
}

// ---------------- scatter into padded logits --------------------------------
__global__ void scatter_out(const float* __restrict__ o2,
                            const void* __restrict__ sizes_raw,
                            float* __restrict__ out)
{
    int tt = blockIdx.x * blockDim.x + threadIdx.x;
    if (tt >= TT) return;
    const long long* s64 = (const long long*)sizes_raw;
    const int*       s32 = (const int*)sizes_raw;
    int is64 = g_sz64;
    long long off = 0; int b = 0;
    while (b < BATCH-1) {
        long long sz = is64 ? s64[b] : (long long)s32[b];
        long long nx = off + sz;
        if (tt < nx) break;
        off = nx; b++;
    }
    int pos = tt - (int)off;
    for (int k = 0; k < ACT; k++)
        out[((size_t)b*MAXS + pos)*ACT + k] = o2[tt*ACT + k];
}

__global__ void fill_kernel(float* __restrict__ p, int n, float v)
{
    int i = blockIdx.x * blockDim.x + threadIdx.x;
    if (i < n) p[i] = v;
}
__global__ void copy_kernel(float* __restrict__ dst, const float* __restrict__ src, int n)
{
    int i = blockIdx.x * blockDim.x + threadIdx.x;
    if (i < n) dst[i] = src[i];
}

// ---------------------------------------------------------------------------
extern "C" void kernel_launch(void* const* d_in, const int* in_sizes, int n_in,
                              void* d_out, int out_size)
{
    const float* data    = (const float*)d_in[0];
    const void*  nonring = d_in[1];
    const void*  nrbidx  = d_in[2];
    const void*  sizes   = d_in[3];
    const float* lin0_w = (const float*)d_in[4];
    const float* lin0_b = (const float*)d_in[5];
    const float* qkv_w  = (const float*)d_in[6];
    const float* qkv_b  = (const float*)d_in[7];
    const float* out_w  = (const float*)d_in[8];
    const float* out_b  = (const float*)d_in[9];
    const float* ff1_w  = (const float*)d_in[10];
    const float* ff1_b  = (const float*)d_in[11];
    const float* ff2_w  = (const float*)d_in[12];
    const float* ff2_b  = (const float*)d_in[13];
    const float* ln1_g  = (const float*)d_in[14];
    const float* ln1_b  = (const float*)d_in[15];
    const float* ln2_g  = (const float*)d_in[16];
    const float* ln2_b  = (const float*)d_in[17];
    const float* s2s_wih = (const float*)d_in[18];
    const float* s2s_whh = (const float*)d_in[19];
    const float* s2s_bih = (const float*)d_in[20];
    const float* s2s_bhh = (const float*)d_in[21];
    const float* mem_wih = (const float*)d_in[22];
    const float* mem_whh = (const float*)d_in[23];
    const float* mem_bih = (const float*)d_in[24];
    const float* mem_bhh = (const float*)d_in[25];
    const float* lin1_w  = (const float*)d_in[26];
    const float* lin1_b  = (const float*)d_in[27];
    const float* lin2_w  = (const float*)d_in[28];
    const float* lin2_b  = (const float*)d_in[29];
    float* out = (float*)d_out;

    float *px, *pqkv, *ptmp, *pqstar, *ph, *pc, *ph1, *pc1, *pfeat, *po1, *po2;
    bf16 *pxh, *pxl, *pah, *pal, *pfh, *pfl;
    bf16 *pwqh, *pwql, *pwoh, *pwol, *pw1h, *pw1l, *pw2h, *pw2l;
    cudaGetSymbolAddress((void**)&px,    g_x);
    cudaGetSymbolAddress((void**)&pxh,   g_xh);
    cudaGetSymbolAddress((void**)&pxl,   g_xl);
    cudaGetSymbolAddress((void**)&pqkv,  g_qkv);
    cudaGetSymbolAddress((void**)&pah,   g_ah);
    cudaGetSymbolAddress((void**)&pal,   g_al);
    cudaGetSymbolAddress((void**)&ptmp,  g_tmp);
    cudaGetSymbolAddress((void**)&pfh,   g_fh);
    cudaGetSymbolAddress((void**)&pfl,   g_fl);
    cudaGetSymbolAddress((void**)&pwqh,  g_wqh);
    cudaGetSymbolAddress((void**)&pwql,  g_wql);
    cudaGetSymbolAddress((void**)&pwoh,  g_woh);
    cudaGetSymbolAddress((void**)&pwol,  g_wol);
    cudaGetSymbolAddress((void**)&pw1h,  g_w1h);
    cudaGetSymbolAddress((void**)&pw1l,  g_w1l);
    cudaGetSymbolAddress((void**)&pw2h,  g_w2h);
    cudaGetSymbolAddress((void**)&pw2l,  g_w2l);
    cudaGetSymbolAddress((void**)&pqstar,g_qstar);
    cudaGetSymbolAddress((void**)&ph,    g_h);
    cudaGetSymbolAddress((void**)&pc,    g_c);
    cudaGetSymbolAddress((void**)&ph1,   g_h1);
    cudaGetSymbolAddress((void**)&pc1,   g_c1);
    cudaGetSymbolAddress((void**)&pfeat, g_feat);
    cudaGetSymbolAddress((void**)&po1,   g_o1);
    cudaGetSymbolAddress((void**)&po2,   g_o2);

    cudaFuncSetAttribute(gemm_mma<0,0>, cudaFuncAttributeMaxDynamicSharedMemorySize, GSM_BYTES);
    cudaFuncSetAttribute(gemm_mma<1,1>, cudaFuncAttributeMaxDynamicSharedMemorySize, GSM_BYTES);

    // 0. integer dtype detection
    detect_dtypes<<<1, 1>>>((const int*)nonring, (const int*)nrbidx, (const int*)sizes);

    // 0b. weight splits (whole stacked tensors in one shot each)
    {
        int n1 = NLAYERS*3*DIMM*DIMM;
        split_kernel<<<(n1+255)/256, 256>>>(qkv_w, pwqh, pwql, n1);
        int n2 = NLAYERS*DIMM*DIMM;
        split_kernel<<<(n2+255)/256, 256>>>(out_w, pwoh, pwol, n2);
        int n3 = NLAYERS*FFD*DIMM;
        split_kernel<<<(n3+255)/256, 256>>>(ff1_w, pw1h, pw1l, n3);
        int n4 = NLAYERS*DIMM*FFD;
        split_kernel<<<(n4+255)/256, 256>>>(ff2_w, pw2h, pw2l, n4);
    }

    // 1. lin0 + relu (+split)
    lin0_kernel<<<ROWS, DIMM>>>(data, lin0_w, lin0_b);

    // 2. encoder layers (mma.sync bf16-split GEMMs on tensor cores)
    for (int l = 0; l < NLAYERS; l++) {
        const float* bq  = qkv_b + (size_t)l*3*DIMM;
        const float* bo  = out_b + (size_t)l*DIMM;
        const float* b1  = ff1_b + (size_t)l*FFD;
        const float* b2  = ff2_b + (size_t)l*DIMM;
        size_t oq = (size_t)l*3*DIMM*DIMM, oo = (size_t)l*DIMM*DIMM;
        size_t o1 = (size_t)l*FFD*DIMM,    o2 = (size_t)l*DIMM*FFD;

        gemm_mma<0,0><<<dim3(3*DIMM/BN, ROWS/BM), 256, GSM_BYTES>>>(
            pxh, pxl, pwqh+oq, pwql+oq, bq, pqkv, (bf16*)0, (bf16*)0, ROWS, 3*DIMM, DIMM);
        attn_kernel<<<ATOMS*NHEADS, 256>>>(pqkv);
        gemm_mma<0,0><<<dim3(DIMM/BN, ROWS/BM), 256, GSM_BYTES>>>(
            pah, pal, pwoh+oo, pwol+oo, bo, ptmp, (bf16*)0, (bf16*)0, ROWS, DIMM, DIMM);
        ln_add<<<ROWS/8, dim3(32,8)>>>(px, ptmp, ln1_g + l*DIMM, ln1_b + l*DIMM);
        gemm_mma<1,1><<<dim3(FFD/BN, ROWS/BM), 256, GSM_BYTES>>>(
            pxh, pxl, pw1h+o1, pw1l+o1, b1, (float*)0, pfh, pfl, ROWS, FFD, DIMM);
        gemm_mma<0,0><<<dim3(DIMM/BN, ROWS/BM), 256, GSM_BYTES>>>(
            pfh, pfl, pw2h+o2, pw2l+o2, b2, ptmp, (bf16*)0, (bf16*)0, ROWS, DIMM, FFD);
        ln_add<<<ROWS/8, dim3(32,8)>>>(px, ptmp, ln2_g + l*DIMM, ln2_b + l*DIMM);
    }

    // 3. Set2Set
    fill_kernel<<<(BATCH*2*DIMM+255)/256, 256>>>(pqstar, BATCH*2*DIMM, 0.f);
    fill_kernel<<<(BATCH*DIMM+255)/256, 256>>>(ph, BATCH*DIMM, 0.f);
    fill_kernel<<<(BATCH*DIMM+255)/256, 256>>>(pc, BATCH*DIMM, 0.f);
    for (int s = 0; s < 6; s++) {
        lstm_step<<<BATCH, 256>>>(pqstar, ph, pc, s2s_wih, s2s_whh, s2s_bih, s2s_bhh);
        s2s_pool<<<BATCH, 256>>>(px, ph, pqstar);
    }

    // 4. memory LSTM
    fill_kernel<<<(BATCH*DIMM+255)/256, 256>>>(ph1, BATCH*DIMM, 0.f);
    fill_kernel<<<(BATCH*DIMM+255)/256, 256>>>(pc1, BATCH*DIMM, 0.f);
    lstm_step<<<BATCH, 256>>>(pqstar, ph1, pc1, mem_wih, mem_whh, mem_bih, mem_bhh);

    // 5. feat gather + lin1 (fp32 SIMT) + lin2
    gather_feat<<<(TT*5*DIMM + 255)/256, 256>>>(px, ph1, nonring, nrbidx, pfeat);
    gemm_nt<1><<<dim3(DIMM/64, (TT+63)/64), 256>>>(pfeat, lin1_w, lin1_b, po1, TT, DIMM, 5*DIMM);
    lin2_kernel<<<(TT*ACT + 255)/256, 256>>>(po1, lin2_w, lin2_b, po2);

    // 6. outputs
    fill_kernel<<<(BATCH*MAXS*ACT + 255)/256, 256>>>(out, BATCH*MAXS*ACT, 0.f);
    scatter_out<<<(TT + 255)/256, 256>>>(po2, sizes, out);
    copy_kernel<<<(BATCH*DIMM + 255)/256, 256>>>(out + BATCH*MAXS*ACT, ph1, BATCH*DIMM);
    copy_kernel<<<(BATCH*DIMM + 255)/256, 256>>>(out + BATCH*MAXS*ACT + BATCH*DIMM, pc1, BATCH*DIMM);
}

// round 16
// speedup vs baseline: 2.2105x; 1.1624x over previous
#include <cuda_runtime.h>
#include <cuda_bf16.h>
#include <math.h>
#include <stdint.h>

#define DIMM 256
#define BATCH 64
#define ATOMS 512
#define ROWS (BATCH*ATOMS)   /* 32768 */
#define NLAYERS 6
#define FFD 2048
#define TT 2016
#define ACT 6
#define MAXS 63
#define NHEADS 8
#define DH 32

typedef __nv_bfloat16 bf16;

// ---------------- scratch (device globals; no allocation allowed) ----------
__device__ float g_x[ROWS*DIMM];          // residual stream fp32
__device__ bf16  g_xh[ROWS*DIMM];         // x split hi
__device__ bf16  g_xl[ROWS*DIMM];         // x split lo
__device__ float g_qkv[ROWS*3*DIMM];      // qkv projections (fp32, attn consumes)
__device__ bf16  g_ah[ROWS*DIMM];         // attn out split hi
__device__ bf16  g_al[ROWS*DIMM];         // attn out split lo
__device__ float g_tmp[ROWS*DIMM];        // proj / ff2 output fp32
__device__ bf16  g_fh[ROWS*FFD];          // ff1 out split hi
__device__ bf16  g_fl[ROWS*FFD];          // ff1 out split lo
__device__ bf16  g_wqh[NLAYERS*3*DIMM*DIMM], g_wql[NLAYERS*3*DIMM*DIMM];
__device__ bf16  g_woh[NLAYERS*DIMM*DIMM],   g_wol[NLAYERS*DIMM*DIMM];
__device__ bf16  g_w1h[NLAYERS*FFD*DIMM],    g_w1l[NLAYERS*FFD*DIMM];
__device__ bf16  g_w2h[NLAYERS*DIMM*FFD],    g_w2l[NLAYERS*DIMM*FFD];
__device__ float g_qstar[BATCH*2*DIMM];
__device__ float g_h[BATCH*DIMM];
__device__ float g_c[BATCH*DIMM];
__device__ float g_h1[BATCH*DIMM];
__device__ float g_c1[BATCH*DIMM];
__device__ float g_feat[TT*5*DIMM];
__device__ float g_o1[TT*DIMM];
__device__ float g_o2[TT*ACT];
__device__ int   g_nr64, g_nb64, g_sz64;

__device__ __forceinline__ float sigmoidf_(float x) { return 1.f / (1.f + expf(-x)); }

__device__ __forceinline__ uint32_t smem_u32(const void* p) {
    uint32_t a;
    asm("{ .reg .u64 t; cvta.to.shared.u64 t, %1; cvt.u32.u64 %0, t; }" : "=r"(a) : "l"(p));
    return a;
}

// ======================= split helpers =====================================
__device__ __forceinline__ void split_bf16(float v, bf16& h, bf16& l) {
    h = __float2bfloat16_rn(v);
    l = __float2bfloat16_rn(v - __bfloat162float(h));
}
__global__ void split_kernel(const float* __restrict__ s, bf16* __restrict__ hi,
                             bf16* __restrict__ lo, int n)
{
    int i = blockIdx.x * blockDim.x + threadIdx.x;
    if (i >= n) return;
    float v = s[i];
    bf16 h, l; split_bf16(v, h, l);
    hi[i] = h; lo[i] = l;
}

// ---------------- integer-dtype detection (deterministic, on-device) -------
__global__ void detect_dtypes(const int* __restrict__ nonring,
                              const int* __restrict__ nrbidx,
                              const int* __restrict__ sizes)
{
    if (threadIdx.x != 0 || blockIdx.x != 0) return;
    int any = 0;
    for (int i = 1; i < 4*TT; i += 2) any |= nonring[i];
    g_nr64 = (any == 0) ? 1 : 0;
    int any2 = 0;
    for (int i = 1; i < TT; i += 2) any2 |= nrbidx[i];
    g_nb64 = (any2 == 0) ? 1 : 0;
    g_sz64 = (sizes[1] == 0) ? 1 : 0;
}

// ======================= mma.sync bf16-split GEMM ==========================
// C[M,N] = A[M,K] * B[N,K]^T (+bias). A,B as bf16 hi/lo splits; fp32 accum;
// AhBh + AhBl + AlBh. Tiles BM=128, BN=128, BK=32, 8 warps (2x4), warp 64x32.
// cp.async double-buffered gmem->smem; ldmatrix.x4 fragment loads.
// Smem rows padded to LDA=40 bf16 (80B -> 20-bank stride): conflict-free.
#define BM 128
#define BN 128
#define BKS 32
#define LDA 40                       /* bf16 elements per smem row */
#define TILE_E (128*LDA)             /* 5120 bf16 per matrix tile */
#define STAGE_E (4*TILE_E)           /* Ah|Al|Bh|Bl */
#define GSM_BYTES (2*STAGE_E*2)      /* 81920 B, double buffered */

#define MMA16816(d, a, b) \
    asm volatile("mma.sync.aligned.m16n8k16.row.col.f32.bf16.bf16.f32 " \
        "{%0,%1,%2,%3}, {%4,%5,%6,%7}, {%8,%9}, {%0,%1,%2,%3};" \
        : "+f"((d)[0]), "+f"((d)[1]), "+f"((d)[2]), "+f"((d)[3]) \
        : "r"((a)[0]), "r"((a)[1]), "r"((a)[2]), "r"((a)[3]), \
          "r"((b)[0]), "r"((b)[1]))
#define CP_ASYNC16(s, g) \
    asm volatile("cp.async.cg.shared.global [%0], [%1], 16;" :: "r"(s), "l"(g))
#define CP_COMMIT() asm volatile("cp.async.commit_group;")
#define CP_WAIT(n)  asm volatile("cp.async.wait_group %0;" :: "n"(n))
#define LDSM_X4(r0, r1, r2, r3, addr) \
    asm volatile("ldmatrix.sync.aligned.m8n8.x4.shared.b16 {%0,%1,%2,%3}, [%4];" \
        : "=r"(r0), "=r"(r1), "=r"(r2), "=r"(r3) : "r"(addr))

template<int RELU, int SPLITOUT>
__global__ __launch_bounds__(256) void gemm_mma(
    const bf16* __restrict__ Ah, const bf16* __restrict__ Al,
    const bf16* __restrict__ Bh, const bf16* __restrict__ Bl,
    const float* __restrict__ bias,
    float* __restrict__ Cf, bf16* __restrict__ Ch, bf16* __restrict__ Cl,
    int M, int N, int K)
{
    extern __shared__ bf16 sm[];
    const uint32_t sbase = smem_u32(sm);
    const int tid  = threadIdx.x;
    const int lane = tid & 31, wid = tid >> 5;
    const int wm = wid >> 2, wn = wid & 3;        // 2 x 4 warp grid
    const int bm = blockIdx.y * BM, bn = blockIdx.x * BN;
    const int g  = lane >> 2, tq = lane & 3;

    float acc[4][4][4];
    #pragma unroll
    for (int mt = 0; mt < 4; mt++)
        #pragma unroll
        for (int nt = 0; nt < 4; nt++)
            #pragma unroll
            for (int r = 0; r < 4; r++) acc[mt][nt][r] = 0.f;

    const int chunks = K / BKS;

    // per-thread gmem/smem chunk coords: i in {tid, tid+256}: row=i>>2, q=(i&3)*8
    const int r0l = tid >> 2,          q0 = (tid & 3) * 8;
    const int r1l = (tid + 256) >> 2,  q1 = ((tid + 256) & 3) * 8;

    // ldmatrix lane addressing
    const int a_row = (( lane >> 3) & 1) * 8 + (lane & 7);   // + mt*16 + wm*64
    const int a_col = (lane >> 4) * 8;                       // + kb
    const int b_sel = lane >> 3;
    const int b_row = (b_sel >> 1) * 8 + (lane & 7);         // + ntp*16 + wn*32
    const int b_col = (b_sel & 1) * 8;                       // + kb

    // ---- async load of one stage ----
    auto load_stage = [&](int st, int kof) {
        uint32_t so = sbase + (uint32_t)st * (STAGE_E * 2);
        {
            uint32_t sa = so + (uint32_t)(r0l * LDA + q0) * 2;
            const bf16* gA = Ah + (size_t)(bm + r0l) * K + kof + q0;
            const bf16* gAl= Al + (size_t)(bm + r0l) * K + kof + q0;
            const bf16* gB = Bh + (size_t)(bn + r0l) * K + kof + q0;
            const bf16* gBl= Bl + (size_t)(bn + r0l) * K + kof + q0;
            CP_ASYNC16(sa,                gA);
            CP_ASYNC16(sa + TILE_E*2,     gAl);
            CP_ASYNC16(sa + 2*TILE_E*2,   gB);
            CP_ASYNC16(sa + 3*TILE_E*2,   gBl);
        }
        {
            uint32_t sa = so + (uint32_t)(r1l * LDA + q1) * 2;
            const bf16* gA = Ah + (size_t)(bm + r1l) * K + kof + q1;
            const bf16* gAl= Al + (size_t)(bm + r1l) * K + kof + q1;
            const bf16* gB = Bh + (size_t)(bn + r1l) * K + kof + q1;
            const bf16* gBl= Bl + (size_t)(bn + r1l) * K + kof + q1;
            CP_ASYNC16(sa,                gA);
            CP_ASYNC16(sa + TILE_E*2,     gAl);
            CP_ASYNC16(sa + 2*TILE_E*2,   gB);
            CP_ASYNC16(sa + 3*TILE_E*2,   gBl);
        }
        CP_COMMIT();
    };

    load_stage(0, 0);

    for (int ch = 0; ch < chunks; ch++) {
        if (ch + 1 < chunks) {
            load_stage((ch + 1) & 1, (ch + 1) * BKS);
            CP_WAIT(1);
        } else {
            CP_WAIT(0);
        }
        __syncthreads();

        const uint32_t tA  = sbase + (uint32_t)(ch & 1) * (STAGE_E * 2);
        const uint32_t tAl = tA + TILE_E*2;
        const uint32_t tBh = tA + 2*TILE_E*2;
        const uint32_t tBl = tA + 3*TILE_E*2;

        #pragma unroll
        for (int ks = 0; ks < 2; ks++) {
            const int kb = ks * 16;
            uint32_t ah[4][4], al[4][4];
            #pragma unroll
            for (int mt = 0; mt < 4; mt++) {
                uint32_t off = (uint32_t)((wm*64 + mt*16 + a_row) * LDA + kb + a_col) * 2;
                LDSM_X4(ah[mt][0], ah[mt][1], ah[mt][2], ah[mt][3], tA  + off);
                LDSM_X4(al[mt][0], al[mt][1], al[mt][2], al[mt][3], tAl + off);
            }
            uint32_t bh[4][2], bl[4][2];
            #pragma unroll
            for (int ntp = 0; ntp < 2; ntp++) {
                uint32_t off = (uint32_t)((wn*32 + ntp*16 + b_row) * LDA + kb + b_col) * 2;
                LDSM_X4(bh[2*ntp][0], bh[2*ntp][1], bh[2*ntp+1][0], bh[2*ntp+1][1], tBh + off);
                LDSM_X4(bl[2*ntp][0], bl[2*ntp][1], bl[2*ntp+1][0], bl[2*ntp+1][1], tBl + off);
            }
            #pragma unroll
            for (int mt = 0; mt < 4; mt++)
                #pragma unroll
                for (int nt = 0; nt < 4; nt++) {
                    MMA16816(acc[mt][nt], ah[mt], bh[nt]);
                    MMA16816(acc[mt][nt], ah[mt], bl[nt]);
                    MMA16816(acc[mt][nt], al[mt], bh[nt]);
                }
        }
        __syncthreads();
    }

    // ---- epilogue: bias (+relu), fp32 or bf16-split output ----
    #pragma unroll
    for (int mt = 0; mt < 4; mt++)
        #pragma unroll
        for (int nt = 0; nt < 4; nt++) {
            int row = bm + wm*64 + mt*16 + g;
            int col = bn + wn*32 + nt*8 + tq*2;
            float b0 = bias[col], b1 = bias[col+1];
            float v0 = acc[mt][nt][0] + b0, v1 = acc[mt][nt][1] + b1;
            float v2 = acc[mt][nt][2] + b0, v3 = acc[mt][nt][3] + b1;
            if (RELU) {
                v0 = fmaxf(v0, 0.f); v1 = fmaxf(v1, 0.f);
                v2 = fmaxf(v2, 0.f); v3 = fmaxf(v3, 0.f);
            }
            if (SPLITOUT) {
                bf16 h0,l0,h1,l1,h2,l2,h3,l3;
                split_bf16(v0,h0,l0); split_bf16(v1,h1,l1);
                split_bf16(v2,h2,l2); split_bf16(v3,h3,l3);
                uint32_t ph01 = (uint32_t)__bfloat16_as_ushort(h1) << 16 | __bfloat16_as_ushort(h0);
                uint32_t pl01 = (uint32_t)__bfloat16_as_ushort(l1) << 16 | __bfloat16_as_ushort(l0);
                uint32_t ph23 = (uint32_t)__bfloat16_as_ushort(h3) << 16 | __bfloat16_as_ushort(h2);
                uint32_t pl23 = (uint32_t)__bfloat16_as_ushort(l3) << 16 | __bfloat16_as_ushort(l2);
                *(uint32_t*)(Ch + (size_t)row*N + col)     = ph01;
                *(uint32_t*)(Cl + (size_t)row*N + col)     = pl01;
                *(uint32_t*)(Ch + (size_t)(row+8)*N + col) = ph23;
                *(uint32_t*)(Cl + (size_t)(row+8)*N + col) = pl23;
            } else {
                *(float2*)(Cf + (size_t)row*N + col)     = make_float2(v0, v1);
                *(float2*)(Cf + (size_t)(row+8)*N + col) = make_float2(v2, v3);
            }
        }
}

// ---------------- generic NT SGEMM (kept for lin1, fp32) -------------------
template<int RELU>
__global__ __launch_bounds__(256) void gemm_nt(
    const float* __restrict__ A, const float* __restrict__ B,
    const float* __restrict__ bias, float* __restrict__ C,
    int M, int N, int K)
{
    __shared__ float As[16][64];
    __shared__ float Bs[16][64];
    const int t  = threadIdx.x;
    const int tx = t & 15, ty = t >> 4;
    const int bm = blockIdx.y * 64, bn = blockIdx.x * 64;
    const int lm = t >> 2;
    const int lk = (t & 3) * 4;
    const bool aval = (bm + lm) < M;
    const bool bval = (bn + lm) < N;
    const float* Arow = A + (size_t)(bm + lm) * K + lk;
    const float* Brow = B + (size_t)(bn + lm) * K + lk;

    float acc[4][4];
    #pragma unroll
    for (int i = 0; i < 4; i++)
        #pragma unroll
        for (int j = 0; j < 4; j++) acc[i][j] = 0.f;

    for (int k0 = 0; k0 < K; k0 += 16) {
        float4 av = aval ? *(const float4*)(Arow + k0) : make_float4(0,0,0,0);
        float4 bv = bval ? *(const float4*)(Brow + k0) : make_float4(0,0,0,0);
        As[lk+0][lm] = av.x; As[lk+1][lm] = av.y; As[lk+2][lm] = av.z; As[lk+3][lm] = av.w;
        Bs[lk+0][lm] = bv.x; Bs[lk+1][lm] = bv.y; Bs[lk+2][lm] = bv.z; Bs[lk+3][lm] = bv.w;
        __syncthreads();
        #pragma unroll
        for (int kk = 0; kk < 16; kk++) {
            float4 a4 = *(const float4*)&As[kk][ty*4];
            float4 b4 = *(const float4*)&Bs[kk][tx*4];
            float ar[4] = {a4.x, a4.y, a4.z, a4.w};
            float br[4] = {b4.x, b4.y, b4.z, b4.w};
            #pragma unroll
            for (int i = 0; i < 4; i++)
                #pragma unroll
                for (int j = 0; j < 4; j++) acc[i][j] += ar[i]*br[j];
        }
        __syncthreads();
    }
    #pragma unroll
    for (int i = 0; i < 4; i++) {
        int m = bm + ty*4 + i;
        if (m >= M) continue;
        #pragma unroll
        for (int j = 0; j < 4; j++) {
            int n = bn + tx*4 + j;
            if (n >= N) continue;
            float v = acc[i][j] + bias[n];
            if (RELU) v = fmaxf(v, 0.f);
            C[(size_t)m * N + n] = v;
        }
    }
}

// ---------------- lin0: (32768,3) -> relu -> x + split ---------------------
__global__ void lin0_kernel(const float* __restrict__ data,
                            const float* __restrict__ w, const float* __restrict__ b)
{
    int r = blockIdx.x, d = threadIdx.x;
    float x0 = data[r*3+0], x1 = data[r*3+1], x2 = data[r*3+2];
    float v = b[d] + x0*w[d*3+0] + x1*w[d*3+1] + x2*w[d*3+2];
    v = fmaxf(v, 0.f);
    size_t o = (size_t)r*DIMM + d;
    g_x[o] = v;
    bf16 h, l; split_bf16(v, h, l);
    g_xh[o] = h; g_xl[o] = l;
}

// ---------------- attention: per (atom n, head h) a 64x64x32 problem -------
__global__ __launch_bounds__(256) void attn_kernel(const float* __restrict__ qkv)
{
    int n = blockIdx.x >> 3, h = blockIdx.x & 7;
    __shared__ float Qs[64][33], Ks[64][33], Vs[64][33];
    __shared__ float St[64][65];
    int tid = threadIdx.x;

    for (int i = tid; i < 64*32; i += 256) {
        int s = i >> 5, d = i & 31;
        size_t base = ((size_t)s*ATOMS + n)*(3*DIMM) + h*DH + d;
        Qs[s][d] = qkv[base];
        Ks[s][d] = qkv[base + DIMM];
        Vs[s][d] = qkv[base + 2*DIMM];
    }
    __syncthreads();

    for (int p = tid; p < 64*64; p += 256) {
        int s = p >> 6, u = p & 63;
        float acc = 0.f;
        #pragma unroll
        for (int d = 0; d < 32; d++) acc += Qs[s][d]*Ks[u][d];
        St[s][u] = acc * 0.17677669529663687f;
    }
    __syncthreads();

    if (tid < 64) {
        float m = -1e30f;
        for (int u = 0; u < 64; u++) m = fmaxf(m, St[tid][u]);
        float sum = 0.f;
        for (int u = 0; u < 64; u++) { float e = expf(St[tid][u]-m); St[tid][u] = e; sum += e; }
        float inv = 1.f / sum;
        for (int u = 0; u < 64; u++) St[tid][u] *= inv;
    }
    __syncthreads();

    for (int p = tid; p < 64*32; p += 256) {
        int s = p >> 5, d = p & 31;
        float acc = 0.f;
        #pragma unroll
        for (int u = 0; u < 64; u++) acc += St[s][u]*Vs[u][d];
        size_t o = ((size_t)s*ATOMS + n)*DIMM + h*DH + d;
        bf16 hh, ll; split_bf16(acc, hh, ll);
        g_ah[o] = hh; g_al[o] = ll;
    }
}

// ---------------- LayerNorm(x + res) -> x fp32 + split ---------------------
__global__ void ln_add(float* __restrict__ x, const float* __restrict__ r,
                       const float* __restrict__ g, const float* __restrict__ b)
{
    int row = blockIdx.x * 8 + threadIdx.y;
    int lane = threadIdx.x;
    size_t base = (size_t)row * DIMM;
    float v[8];
    float s = 0.f;
    #pragma unroll
    for (int i = 0; i < 8; i++) {
        v[i] = x[base + i*32 + lane] + r[base + i*32 + lane];
        s += v[i];
    }
    #pragma unroll
    for (int o = 16; o; o >>= 1) s += __shfl_xor_sync(0xffffffffu, s, o);
    float mean = s * (1.f/256.f);
    float vs = 0.f;
    #pragma unroll
    for (int i = 0; i < 8; i++) { float d = v[i]-mean; vs += d*d; }
    #pragma unroll
    for (int o = 16; o; o >>= 1) vs += __shfl_xor_sync(0xffffffffu, vs, o);
    float rstd = rsqrtf(vs * (1.f/256.f) + 1e-5f);
    #pragma unroll
    for (int i = 0; i < 8; i++) {
        float val = (v[i]-mean)*rstd*g[i*32+lane] + b[i*32+lane];
        size_t o = base + i*32 + lane;
        x[o] = val;
        bf16 hh, ll; split_bf16(val, hh, ll);
        g_xh[o] = hh; g_xl[o] = ll;
    }
}

// ---------------- LSTM step (torch gate order i,f,g,o) ---------------------
__global__ __launch_bounds__(256) void lstm_step(
    const float* __restrict__ x,
    float* __restrict__ h, float* __restrict__ c,
    const float* __restrict__ wih, const float* __restrict__ whh,
    const float* __restrict__ bih, const float* __restrict__ bhh)
{
    int b = blockIdx.x, tid = threadIdx.x;
    __shared__ float xs[512], hs[256], gates[1024];
    for (int i = tid; i < 512; i += 256) xs[i] = x[b*512 + i];
    hs[tid] = h[b*256 + tid];
    __syncthreads();
    for (int gi = tid; gi < 1024; gi += 256) {
        const float* wr = wih + (size_t)gi*512;
        const float* hr = whh + (size_t)gi*256;
        float acc = bih[gi] + bhh[gi];
        for (int k = 0; k < 512; k++) acc += xs[k]*wr[k];
        for (int k = 0; k < 256; k++) acc += hs[k]*hr[k];
        gates[gi] = acc;
    }
    __syncthreads();
    float iv = gates[tid], fv = gates[256+tid], gv = gates[512+tid], ov = gates[768+tid];
    float cn = sigmoidf_(fv)*c[b*256+tid] + sigmoidf_(iv)*tanhf(gv);
    float hn = sigmoidf_(ov)*tanhf(cn);
    c[b*256+tid] = cn;
    h[b*256+tid] = hn;
}

// ---------------- Set2Set pooling ------------------------------------------
__global__ __launch_bounds__(256) void s2s_pool(const float* __restrict__ x3,
                                                const float* __restrict__ h,
                                                float* __restrict__ qstar)
{
    int b = blockIdx.x, tid = threadIdx.x;
    int lane = tid & 31, wid = tid >> 5;
    __shared__ float hs[256];
    __shared__ float w[512];
    __shared__ float rbuf[256];
    hs[tid] = h[b*256 + tid];
    __syncthreads();
    for (int a = wid; a < 512; a += 8) {
        const float* row = x3 + ((size_t)b*ATOMS + a)*DIMM;
        float p = 0.f;
        #pragma unroll
        for (int i = 0; i < 8; i++) p += row[lane + i*32]*hs[lane + i*32];
        #pragma unroll
        for (int o = 16; o; o >>= 1) p += __shfl_xor_sync(0xffffffffu, p, o);
        if (lane == 0) w[a] = p;
    }
    __syncthreads();
    rbuf[tid] = fmaxf(w[tid], w[tid+256]);
    __syncthreads();
    for (int s = 128; s; s >>= 1) { if (tid < s) rbuf[tid] = fmaxf(rbuf[tid], rbuf[tid+s]); __syncthreads(); }
    float mx = rbuf[0];
    __syncthreads();
    float e1 = expf(w[tid]-mx), e2 = expf(w[tid+256]-mx);
    w[tid] = e1; w[tid+256] = e2;
    rbuf[tid] = e1 + e2;
    __syncthreads();
    for (int s = 128; s; s >>= 1) { if (tid < s) rbuf[tid] += rbuf[tid+s]; __syncthreads(); }
    float inv = 1.f / rbuf[0];
    float acc = 0.f;
    for (int a = 0; a < 512; a++) acc += w[a]*x3[((size_t)b*ATOMS + a)*DIMM + tid];
    qstar[b*512 + tid]       = hs[tid];
    qstar[b*512 + 256 + tid] = acc * inv;
}

// ---------------- feat gather ----------------------------------------------
__global__ void gather_feat(const float* __restrict__ out_flat,
                            const float* __restrict__ h1,
                            const void* __restrict__ nonring_raw,
                            const void* __restrict__ nrbidx_raw,
                            float* __restrict__ feat)
{
    int idx = blockIdx.x * blockDim.x + threadIdx.x;
    if (idx >= TT*5*DIMM) return;
    int d   = idx / (5*TT);
    int rem = idx % (5*TT);
    int tt  = rem / 5;
    int s   = rem % 5;
    float v;
    if (s == 0) {
        int bb = g_nb64 ? (int)((const long long*)nrbidx_raw)[tt]
                        : ((const int*)nrbidx_raw)[tt];
        v = h1[bb*DIMM + d];
    } else {
        int j = (s-1)*TT + tt;
        int src = g_nr64 ? (int)((const long long*)nonring_raw)[j]
                         : ((const int*)nonring_raw)[j];
        v = out_flat[(size_t)src*DIMM + d];
    }
    feat[idx] = v;
}

// ---------------- lin2 ------------------------------------------------------
__global__ void lin2_kernel(const float* __restrict__ o1, const float* __restrict__ w,
                            const float* __restrict__ b, float* __restrict__ o2)
{
    int idx = blockIdx.x * blockDim.x + threadIdx.x;
    if (idx >= TT*ACT) return;
    int tt = idx / ACT, j = idx % ACT;
    const float* row = o1 + (size_t)tt*DIMM;
    const float* wr  = w + (size_t)j*DIMM;
    float acc = b[j];
    for (int k = 0; k < DIMM; k++) acc += row[k]*wr[k];
    o2[idx] = acc;
}

// ---------------- scatter into padded logits --------------------------------
__global__ void scatter_out(const float* __restrict__ o2,
                            const void* __restrict__ sizes_raw,
                            float* __restrict__ out)
{
    int tt = blockIdx.x * blockDim.x + threadIdx.x;
    if (tt >= TT) return;
    const long long* s64 = (const long long*)sizes_raw;
    const int*       s32 = (const int*)sizes_raw;
    int is64 = g_sz64;
    long long off = 0; int b = 0;
    while (b < BATCH-1) {
        long long sz = is64 ? s64[b] : (long long)s32[b];
        long long nx = off + sz;
        if (tt < nx) break;
        off = nx; b++;
    }
    int pos = tt - (int)off;
    for (int k = 0; k < ACT; k++)
        out[((size_t)b*MAXS + pos)*ACT + k] = o2[tt*ACT + k];
}

__global__ void fill_kernel(float* __restrict__ p, int n, float v)
{
    int i = blockIdx.x * blockDim.x + threadIdx.x;
    if (i < n) p[i] = v;
}
__global__ void copy_kernel(float* __restrict__ dst, const float* __restrict__ src, int n)
{
    int i = blockIdx.x * blockDim.x + threadIdx.x;
    if (i < n) dst[i] = src[i];
}

// ---------------------------------------------------------------------------
extern "C" void kernel_launch(void* const* d_in, const int* in_sizes, int n_in,
                              void* d_out, int out_size)
{
    const float* data    = (const float*)d_in[0];
    const void*  nonring = d_in[1];
    const void*  nrbidx  = d_in[2];
    const void*  sizes   = d_in[3];
    const float* lin0_w = (const float*)d_in[4];
    const float* lin0_b = (const float*)d_in[5];
    const float* qkv_w  = (const float*)d_in[6];
    const float* qkv_b  = (const float*)d_in[7];
    const float* out_w  = (const float*)d_in[8];
    const float* out_b  = (const float*)d_in[9];
    const float* ff1_w  = (const float*)d_in[10];
    const float* ff1_b  = (const float*)d_in[11];
    const float* ff2_w  = (const float*)d_in[12];
    const float* ff2_b  = (const float*)d_in[13];
    const float* ln1_g  = (const float*)d_in[14];
    const float* ln1_b  = (const float*)d_in[15];
    const float* ln2_g  = (const float*)d_in[16];
    const float* ln2_b  = (const float*)d_in[17];
    const float* s2s_wih = (const float*)d_in[18];
    const float* s2s_whh = (const float*)d_in[19];
    const float* s2s_bih = (const float*)d_in[20];
    const float* s2s_bhh = (const float*)d_in[21];
    const float* mem_wih = (const float*)d_in[22];
    const float* mem_whh = (const float*)d_in[23];
    const float* mem_bih = (const float*)d_in[24];
    const float* mem_bhh = (const float*)d_in[25];
    const float* lin1_w  = (const float*)d_in[26];
    const float* lin1_b  = (const float*)d_in[27];
    const float* lin2_w  = (const float*)d_in[28];
    const float* lin2_b  = (const float*)d_in[29];
    float* out = (float*)d_out;

    float *px, *pqkv, *ptmp, *pqstar, *ph, *pc, *ph1, *pc1, *pfeat, *po1, *po2;
    bf16 *pxh, *pxl, *pah, *pal, *pfh, *pfl;
    bf16 *pwqh, *pwql, *pwoh, *pwol, *pw1h, *pw1l, *pw2h, *pw2l;
    cudaGetSymbolAddress((void**)&px,    g_x);
    cudaGetSymbolAddress((void**)&pxh,   g_xh);
    cudaGetSymbolAddress((void**)&pxl,   g_xl);
    cudaGetSymbolAddress((void**)&pqkv,  g_qkv);
    cudaGetSymbolAddress((void**)&pah,   g_ah);
    cudaGetSymbolAddress((void**)&pal,   g_al);
    cudaGetSymbolAddress((void**)&ptmp,  g_tmp);
    cudaGetSymbolAddress((void**)&pfh,   g_fh);
    cudaGetSymbolAddress((void**)&pfl,   g_fl);
    cudaGetSymbolAddress((void**)&pwqh,  g_wqh);
    cudaGetSymbolAddress((void**)&pwql,  g_wql);
    cudaGetSymbolAddress((void**)&pwoh,  g_woh);
    cudaGetSymbolAddress((void**)&pwol,  g_wol);
    cudaGetSymbolAddress((void**)&pw1h,  g_w1h);
    cudaGetSymbolAddress((void**)&pw1l,  g_w1l);
    cudaGetSymbolAddress((void**)&pw2h,  g_w2h);
    cudaGetSymbolAddress((void**)&pw2l,  g_w2l);
    cudaGetSymbolAddress((void**)&pqstar,g_qstar);
    cudaGetSymbolAddress((void**)&ph,    g_h);
    cudaGetSymbolAddress((void**)&pc,    g_c);
    cudaGetSymbolAddress((void**)&ph1,   g_h1);
    cudaGetSymbolAddress((void**)&pc1,   g_c1);
    cudaGetSymbolAddress((void**)&pfeat, g_feat);
    cudaGetSymbolAddress((void**)&po1,   g_o1);
    cudaGetSymbolAddress((void**)&po2,   g_o2);

    cudaFuncSetAttribute(gemm_mma<0,0>, cudaFuncAttributeMaxDynamicSharedMemorySize, GSM_BYTES);
    cudaFuncSetAttribute(gemm_mma<1,1>, cudaFuncAttributeMaxDynamicSharedMemorySize, GSM_BYTES);

    // 0. integer dtype detection
    detect_dtypes<<<1, 1>>>((const int*)nonring, (const int*)nrbidx, (const int*)sizes);

    // 0b. weight splits (whole stacked tensors in one shot each)
    {
        int n1 = NLAYERS*3*DIMM*DIMM;
        split_kernel<<<(n1+255)/256, 256>>>(qkv_w, pwqh, pwql, n1);
        int n2 = NLAYERS*DIMM*DIMM;
        split_kernel<<<(n2+255)/256, 256>>>(out_w, pwoh, pwol, n2);
        int n3 = NLAYERS*FFD*DIMM;
        split_kernel<<<(n3+255)/256, 256>>>(ff1_w, pw1h, pw1l, n3);
        int n4 = NLAYERS*DIMM*FFD;
        split_kernel<<<(n4+255)/256, 256>>>(ff2_w, pw2h, pw2l, n4);
    }

    // 1. lin0 + relu (+split)
    lin0_kernel<<<ROWS, DIMM>>>(data, lin0_w, lin0_b);

    // 2. encoder layers (mma.sync bf16-split GEMMs on tensor cores)
    for (int l = 0; l < NLAYERS; l++) {
        const float* bq  = qkv_b + (size_t)l*3*DIMM;
        const float* bo  = out_b + (size_t)l*DIMM;
        const float* b1  = ff1_b + (size_t)l*FFD;
        const float* b2  = ff2_b + (size_t)l*DIMM;
        size_t oq = (size_t)l*3*DIMM*DIMM, oo = (size_t)l*DIMM*DIMM;
        size_t o1 = (size_t)l*FFD*DIMM,    o2 = (size_t)l*DIMM*FFD;

        gemm_mma<0,0><<<dim3(3*DIMM/BN, ROWS/BM), 256, GSM_BYTES>>>(
            pxh, pxl, pwqh+oq, pwql+oq, bq, pqkv, (bf16*)0, (bf16*)0, ROWS, 3*DIMM, DIMM);
        attn_kernel<<<ATOMS*NHEADS, 256>>>(pqkv);
        gemm_mma<0,0><<<dim3(DIMM/BN, ROWS/BM), 256, GSM_BYTES>>>(
            pah, pal, pwoh+oo, pwol+oo, bo, ptmp, (bf16*)0, (bf16*)0, ROWS, DIMM, DIMM);
        ln_add<<<ROWS/8, dim3(32,8)>>>(px, ptmp, ln1_g + l*DIMM, ln1_b + l*DIMM);
        gemm_mma<1,1><<<dim3(FFD/BN, ROWS/BM), 256, GSM_BYTES>>>(
            pxh, pxl, pw1h+o1, pw1l+o1, b1, (float*)0, pfh, pfl, ROWS, FFD, DIMM);
        gemm_mma<0,0><<<dim3(DIMM/BN, ROWS/BM), 256, GSM_BYTES>>>(
            pfh, pfl, pw2h+o2, pw2l+o2, b2, ptmp, (bf16*)0, (bf16*)0, ROWS, DIMM, FFD);
        ln_add<<<ROWS/8, dim3(32,8)>>>(px, ptmp, ln2_g + l*DIMM, ln2_b + l*DIMM);
    }

    // 3. Set2Set
    fill_kernel<<<(BATCH*2*DIMM+255)/256, 256>>>(pqstar, BATCH*2*DIMM, 0.f);
    fill_kernel<<<(BATCH*DIMM+255)/256, 256>>>(ph, BATCH*DIMM, 0.f);
    fill_kernel<<<(BATCH*DIMM+255)/256, 256>>>(pc, BATCH*DIMM, 0.f);
    for (int s = 0; s < 6; s++) {
        lstm_step<<<BATCH, 256>>>(pqstar, ph, pc, s2s_wih, s2s_whh, s2s_bih, s2s_bhh);
        s2s_pool<<<BATCH, 256>>>(px, ph, pqstar);
    }

    // 4. memory LSTM
    fill_kernel<<<(BATCH*DIMM+255)/256, 256>>>(ph1, BATCH*DIMM, 0.f);
    fill_kernel<<<(BATCH*DIMM+255)/256, 256>>>(pc1, BATCH*DIMM, 0.f);
    lstm_step<<<BATCH, 256>>>(pqstar, ph1, pc1, mem_wih, mem_whh, mem_bih, mem_bhh);

    // 5. feat gather + lin1 (fp32 SIMT) + lin2
    gather_feat<<<(TT*5*DIMM + 255)/256, 256>>>(px, ph1, nonring, nrbidx, pfeat);
    gemm_nt<1><<<dim3(DIMM/64, (TT+63)/64), 256>>>(pfeat, lin1_w, lin1_b, po1, TT, DIMM, 5*DIMM);
    lin2_kernel<<<(TT*ACT + 255)/256, 256>>>(po1, lin2_w, lin2_b, po2);

    // 6. outputs
    fill_kernel<<<(BATCH*MAXS*ACT + 255)/256, 256>>>(out, BATCH*MAXS*ACT, 0.f);
    scatter_out<<<(TT + 255)/256, 256>>>(po2, sizes, out);
    copy_kernel<<<(BATCH*DIMM + 255)/256, 256>>>(out + BATCH*MAXS*ACT, ph1, BATCH*DIMM);
    copy_kernel<<<(BATCH*DIMM + 255)/256, 256>>>(out + BATCH*MAXS*ACT + BATCH*DIMM, pc1, BATCH*DIMM);
}